// round 1
// baseline (speedup 1.0000x reference)
#include <cuda_runtime.h>
#include <cstdint>
#include <cstddef>

// Problem constants (AttentionPool: B=8, T=4096, D=1024, G=64)
#define B_  8
#define T_  4096
#define D_  1024
#define G_  64
#define BT_ (B_ * T_)           // 32768 tokens
#define BG_ (B_ * G_)           // 512 (b,g) pairs
#define EPS_ 1.1920928955078125e-07f   // finfo(float32).eps
#define INV_SQRT_D_ (1.0f / 32.0f)

// ---------------------------------------------------------------------------
// Device scratch (static — no allocations allowed)
// ---------------------------------------------------------------------------
__device__ float  g_qk_part[16 * D_];     // partial Wk^T q
__device__ float  g_qkd[D_];              // norm_w * (Wk^T q)
__device__ float  g_score[BT_];           // per-token score
__device__ float  g_invrms[BT_];          // per-token 1/rms
__device__ float  g_m[BG_];               // per (b,g) max
__device__ float  g_rden[BG_];            // per (b,g) 1/denom
__device__ int    g_gid[BT_];             // normalized int32 group ids
__device__ int    g_is64;                 // group_id dtype flag
__device__ float2 g_wg[BT_];              // {coef, group_as_bits} per token
__device__ float  g_p[BG_ * D_];          // pooled h (incl norm_w)
__device__ float  g_out_part[4][BG_ * D_];// split-K GEMM partials

// ---------------------------------------------------------------------------
// Kernel 1: detect whether group_id is int64 (hi words all zero) or int32
// ---------------------------------------------------------------------------
__global__ void detect_kernel(const unsigned int* __restrict__ raw) {
    unsigned int acc = 0;
    for (int i = threadIdx.x; i < BT_ / 2; i += 256) acc |= raw[2 * i + 1];
    #pragma unroll
    for (int o = 16; o; o >>= 1) acc |= __shfl_xor_sync(0xffffffffu, acc, o);
    __shared__ unsigned int s[8];
    if ((threadIdx.x & 31) == 0) s[threadIdx.x >> 5] = acc;
    __syncthreads();
    if (threadIdx.x == 0) {
        unsigned int t = 0;
        #pragma unroll
        for (int i = 0; i < 8; i++) t |= s[i];
        g_is64 = (t == 0) ? 1 : 0;
    }
}

// Kernel 2: normalize group ids to int32
__global__ void convert_kernel(const unsigned int* __restrict__ raw) {
    int t = blockIdx.x * 256 + threadIdx.x;
    if (t < BT_) {
        int v = g_is64 ? (int)raw[2 * t] : (int)raw[t];
        g_gid[t] = v;
    }
}

// ---------------------------------------------------------------------------
// Kernel 3/4: qk[d] = sum_e query[e] * Wk[e,d], then *= norm_w[d]
// ---------------------------------------------------------------------------
__global__ void __launch_bounds__(128) qk_part_kernel(
    const float* __restrict__ query, const float* __restrict__ Wk) {
    int d  = blockIdx.x * 128 + threadIdx.x;   // 8 blocks in x
    int e0 = blockIdx.y * 64;                  // 16 splits in y
    float s = 0.f;
    #pragma unroll 8
    for (int e = e0; e < e0 + 64; e++) s += query[e] * Wk[(size_t)e * D_ + d];
    g_qk_part[blockIdx.y * D_ + d] = s;
}

__global__ void __launch_bounds__(128) qk_finish_kernel(const float* __restrict__ norm_w) {
    int d = blockIdx.x * 128 + threadIdx.x;
    float s = 0.f;
    #pragma unroll
    for (int p = 0; p < 16; p++) s += g_qk_part[p * D_ + d];
    g_qkd[d] = s * norm_w[d];
}

// ---------------------------------------------------------------------------
// Kernel 5: per-token stats — sum(x^2) and x . qkd  (one 128-thr block/token)
// ---------------------------------------------------------------------------
__global__ void __launch_bounds__(128) token_stats_kernel(const float* __restrict__ x) {
    int tok = blockIdx.x;
    int tid = threadIdx.x;
    const float4* xt = (const float4*)(x + (size_t)tok * D_);
    const float4* qk = (const float4*)g_qkd;
    float ss = 0.f, dq = 0.f;
    #pragma unroll
    for (int r = 0; r < 2; r++) {
        int i = r * 128 + tid;
        float4 v = xt[i];
        float4 q = qk[i];
        ss += v.x * v.x + v.y * v.y + v.z * v.z + v.w * v.w;
        dq += v.x * q.x + v.y * q.y + v.z * q.z + v.w * q.w;
    }
    #pragma unroll
    for (int o = 16; o; o >>= 1) {
        ss += __shfl_xor_sync(0xffffffffu, ss, o);
        dq += __shfl_xor_sync(0xffffffffu, dq, o);
    }
    __shared__ float sS[4], sD[4];
    if ((tid & 31) == 0) { sS[tid >> 5] = ss; sD[tid >> 5] = dq; }
    __syncthreads();
    if (tid == 0) {
        float S = sS[0] + sS[1] + sS[2] + sS[3];
        float Q = sD[0] + sD[1] + sD[2] + sD[3];
        float ir = rsqrtf(S * (1.0f / (float)D_) + EPS_);
        g_invrms[tok] = ir;
        g_score[tok]  = Q * ir * INV_SQRT_D_;
    }
}

// ---------------------------------------------------------------------------
// Kernel 6: segment softmax stats per (b,g): max and 1/denom
// ---------------------------------------------------------------------------
__global__ void __launch_bounds__(128) seg_softmax_kernel() {
    int b = blockIdx.x >> 6;
    int g = blockIdx.x & 63;
    int tid = threadIdx.x;
    const float* sc  = g_score + b * T_;
    const int*   gid = g_gid   + b * T_;

    float mx = -3.402823466e38f;
    for (int t = tid; t < T_; t += 128)
        if (gid[t] == g) mx = fmaxf(mx, sc[t]);
    #pragma unroll
    for (int o = 16; o; o >>= 1) mx = fmaxf(mx, __shfl_xor_sync(0xffffffffu, mx, o));
    __shared__ float sm[4];
    if ((tid & 31) == 0) sm[tid >> 5] = mx;
    __syncthreads();
    mx = fmaxf(fmaxf(sm[0], sm[1]), fmaxf(sm[2], sm[3]));  // broadcast to all

    float sum = 0.f;
    for (int t = tid; t < T_; t += 128)
        if (gid[t] == g) sum += __expf(sc[t] - mx);
    #pragma unroll
    for (int o = 16; o; o >>= 1) sum += __shfl_xor_sync(0xffffffffu, sum, o);
    __shared__ float ssum[4];
    if ((tid & 31) == 0) ssum[tid >> 5] = sum;
    __syncthreads();
    if (tid == 0) {
        float S = ssum[0] + ssum[1] + ssum[2] + ssum[3];
        g_m[blockIdx.x]    = (mx > -1e37f) ? mx : 0.f;
        g_rden[blockIdx.x] = (S > 0.f) ? (1.0f / S) : 0.f;
    }
}

// ---------------------------------------------------------------------------
// Kernel 7: per-token coefficient  coef = exp(s - m[g]) / denom * invrms
// packed with the group id into a float2 for a single LDG.64 in the pool.
// ---------------------------------------------------------------------------
__global__ void coef_kernel() {
    int t = blockIdx.x * 256 + threadIdx.x;
    if (t < BT_) {
        int b  = t >> 12;
        int g  = g_gid[t];
        int bg = b * G_ + g;
        float c = __expf(g_score[t] - g_m[bg]) * g_rden[bg] * g_invrms[t];
        g_wg[t] = make_float2(c, __int_as_float(g));
    }
}

// ---------------------------------------------------------------------------
// Kernel 8: group pooling  p[b,g,d] = sum_t coef * x[b,t,d], *norm_w at flush.
// Grid (32 d-chunks of 32, 8 batches). 128 threads = 4 warps.
// Per-warp private accumulators x 4 parity buffers break the smem RMW chain:
// 4 warps * 4 parity * 64 groups * 32 cols * 4B = 128 KB dynamic smem.
// Warp w handles tokens t == w (mod 4); parity = (t/4) & 3.
// Fully deterministic: each (g, col) slot owned by exactly one thread.
// ---------------------------------------------------------------------------
__global__ void __launch_bounds__(128) pool_kernel(
    const float* __restrict__ x, const float* __restrict__ norm_w) {
    extern __shared__ float acc[];   // [4 warps][4 parity][64*32]
    int tid  = threadIdx.x;
    int lane = tid & 31;
    int w    = tid >> 5;
    int ch   = blockIdx.x;           // 0..31 (column chunk of 32)
    int b    = blockIdx.y;           // 0..7

    for (int i = tid; i < 4 * 4 * G_ * 32; i += 128) acc[i] = 0.f;
    __syncthreads();

    float* aw = acc + w * (4 * G_ * 32);      // this warp's 4 parity buffers
    const float2* wg = g_wg + b * T_;
    const float*  xb = x + (size_t)b * T_ * D_ + (size_t)ch * 32 + lane;

    for (int j = w; j < T_; j += 16) {        // 4 tokens per iteration
        float2 w0 = wg[j];
        float2 w1 = wg[j + 4];
        float2 w2 = wg[j + 8];
        float2 w3 = wg[j + 12];
        float x0 = xb[(size_t)j * D_];
        float x1 = xb[(size_t)(j + 4) * D_];
        float x2 = xb[(size_t)(j + 8) * D_];
        float x3 = xb[(size_t)(j + 12) * D_];
        int i0 = __float_as_int(w0.y) * 32 + lane;
        int i1 = __float_as_int(w1.y) * 32 + lane + 2048;
        int i2 = __float_as_int(w2.y) * 32 + lane + 4096;
        int i3 = __float_as_int(w3.y) * 32 + lane + 6144;
        // group all loads before all stores: parity chains overlap
        float v0 = aw[i0];
        float v1 = aw[i1];
        float v2 = aw[i2];
        float v3 = aw[i3];
        aw[i0] = fmaf(w0.x, x0, v0);
        aw[i1] = fmaf(w1.x, x1, v1);
        aw[i2] = fmaf(w2.x, x2, v2);
        aw[i3] = fmaf(w3.x, x3, v3);
    }
    __syncthreads();

    // Flush: sum 16 buffers per (g, col), apply norm_w, write p.
    float* pout = g_p + (size_t)b * G_ * D_ + (size_t)ch * 32;
    for (int i = tid; i < G_ * 32; i += 128) {
        int g = i >> 5, c = i & 31;
        float s = 0.f;
        #pragma unroll
        for (int ww = 0; ww < 4; ww++)
            #pragma unroll
            for (int q = 0; q < 4; q++)
                s += acc[ww * 8192 + q * 2048 + g * 32 + c];
        pout[(size_t)g * D_ + c] = s * norm_w[ch * 32 + c];
    }
}

// ---------------------------------------------------------------------------
// Kernel 9: out = p @ Wv^T, split-K=4.  M=512, N=1024, K=1024.
// 128x128 tiles, BK=8, 256 threads, 8x8 microtiles (1 B smem / FMA — balanced).
// Grid (N/128=8, M/128=4, splitK=4) = 128 CTAs.
// ---------------------------------------------------------------------------
__global__ void __launch_bounds__(256) gemm_kernel(const float* __restrict__ Wv) {
    __shared__ float As[8][128];
    __shared__ float Bs[8][128];
    int tid = threadIdx.x;
    int bn = blockIdx.x, bm = blockIdx.y, ks = blockIdx.z;
    int row = tid >> 1;            // 0..127 (loader row)
    int kq  = (tid & 1) * 4;       // loader k quad
    int tx = tid & 15, ty = tid >> 4;

    const float* Ag = g_p + (size_t)(bm * 128 + row) * D_ + ks * 256 + kq;
    const float* Bg = Wv  + (size_t)(bn * 128 + row) * D_ + ks * 256 + kq;

    float acc[8][8];
    #pragma unroll
    for (int r = 0; r < 8; r++)
        #pragma unroll
        for (int c = 0; c < 8; c++) acc[r][c] = 0.f;

    for (int k0 = 0; k0 < 256; k0 += 8) {
        float4 av = *(const float4*)(Ag + k0);
        float4 bv = *(const float4*)(Bg + k0);
        __syncthreads();
        As[kq + 0][row] = av.x; As[kq + 1][row] = av.y;
        As[kq + 2][row] = av.z; As[kq + 3][row] = av.w;
        Bs[kq + 0][row] = bv.x; Bs[kq + 1][row] = bv.y;
        Bs[kq + 2][row] = bv.z; Bs[kq + 3][row] = bv.w;
        __syncthreads();
        #pragma unroll
        for (int kk = 0; kk < 8; kk++) {
            float4 a0 = *(const float4*)&As[kk][ty * 8];
            float4 a1 = *(const float4*)&As[kk][ty * 8 + 4];
            float4 b0 = *(const float4*)&Bs[kk][tx * 8];
            float4 b1 = *(const float4*)&Bs[kk][tx * 8 + 4];
            float a[8] = {a0.x, a0.y, a0.z, a0.w, a1.x, a1.y, a1.z, a1.w};
            float bb[8] = {b0.x, b0.y, b0.z, b0.w, b1.x, b1.y, b1.z, b1.w};
            #pragma unroll
            for (int r = 0; r < 8; r++)
                #pragma unroll
                for (int c = 0; c < 8; c++)
                    acc[r][c] = fmaf(a[r], bb[c], acc[r][c]);
        }
    }

    float* op = g_out_part[ks] + (size_t)(bm * 128 + ty * 8) * D_ + bn * 128 + tx * 8;
    #pragma unroll
    for (int r = 0; r < 8; r++) {
        *(float4*)(op + (size_t)r * D_)     = make_float4(acc[r][0], acc[r][1], acc[r][2], acc[r][3]);
        *(float4*)(op + (size_t)r * D_ + 4) = make_float4(acc[r][4], acc[r][5], acc[r][6], acc[r][7]);
    }
}

// Kernel 10: fixed-order split-K reduction into d_out
__global__ void gemm_reduce_kernel(float* __restrict__ out) {
    int idx = blockIdx.x * 256 + threadIdx.x;
    if (idx < BG_ * D_) {
        float s = g_out_part[0][idx] + g_out_part[1][idx]
                + g_out_part[2][idx] + g_out_part[3][idx];
        out[idx] = s;
    }
}

// ---------------------------------------------------------------------------
// Launch
// ---------------------------------------------------------------------------
extern "C" void kernel_launch(void* const* d_in, const int* in_sizes, int n_in,
                              void* d_out, int out_size) {
    const float* x = nullptr;
    const void*  gid = nullptr;
    const float* query = nullptr;
    const float* norm_w = nullptr;
    const float* Wk = nullptr;
    const float* Wv = nullptr;

    // Map inputs by element count (robust to presence/absence of num_groups).
    for (int i = 0; i < n_in; i++) {
        int s = in_sizes[i];
        if (s == B_ * T_ * D_)      x = (const float*)d_in[i];
        else if (s == BT_)          gid = d_in[i];
        else if (s == D_) {
            if (!query) query = (const float*)d_in[i];
            else        norm_w = (const float*)d_in[i];
        } else if (s == D_ * D_) {
            if (!Wk) Wk = (const float*)d_in[i];
            else     Wv = (const float*)d_in[i];
        }
    }
    if (!x || !gid || !query || !norm_w || !Wk || !Wv) return;

    float* out = (float*)d_out;
    (void)out_size;

    cudaFuncSetAttribute(pool_kernel,
                         cudaFuncAttributeMaxDynamicSharedMemorySize, 131072);

    detect_kernel<<<1, 256>>>((const unsigned int*)gid);
    convert_kernel<<<(BT_ + 255) / 256, 256>>>((const unsigned int*)gid);
    qk_part_kernel<<<dim3(8, 16), 128>>>(query, Wk);
    qk_finish_kernel<<<8, 128>>>(norm_w);
    token_stats_kernel<<<BT_, 128>>>(x);
    seg_softmax_kernel<<<BG_, 128>>>();
    coef_kernel<<<(BT_ + 255) / 256, 256>>>();
    pool_kernel<<<dim3(32, 8), 128, 131072>>>(x, norm_w);
    gemm_kernel<<<dim3(8, 4, 4), 256>>>(Wv);
    gemm_reduce_kernel<<<(BG_ * D_ + 255) / 256, 256>>>(out);
}

// round 3
// speedup vs baseline: 1.7043x; 1.7043x over previous
#include <cuda_runtime.h>
#include <cstdint>
#include <cstddef>

// Problem constants (AttentionPool: B=8, T=4096, D=1024, G=64)
#define B_  8
#define T_  4096
#define D_  1024
#define G_  64
#define BT_ (B_ * T_)           // 32768 tokens
#define BG_ (B_ * G_)           // 512 (b,g) pairs
#define EPS_ 1.1920928955078125e-07f   // finfo(float32).eps
#define INV_SQRT_D_ (1.0f / 32.0f)

typedef unsigned long long u64;

// ---------------------------------------------------------------------------
// Device scratch (static — no allocations allowed)
// ---------------------------------------------------------------------------
__device__ float  g_qk_part[16 * D_];     // partial Wk^T q
__device__ float  g_qkd[D_];              // norm_w * (Wk^T q)
__device__ float  g_score[BT_];           // per-token score
__device__ float  g_invrms[BT_];          // per-token 1/rms
__device__ float  g_m[BG_];               // per (b,g) max
__device__ float  g_rden[BG_];            // per (b,g) 1/denom
__device__ int    g_gid[BT_];             // normalized int32 group ids
__device__ int    g_is64;                 // group_id dtype flag
__device__ float2 g_wg[BT_];              // {coef, group_as_bits} per token
__device__ float  g_p[BG_ * D_];          // pooled h (incl norm_w)
__device__ float  g_out_part[4][BG_ * D_];// split-K GEMM partials

// ---------------------------------------------------------------------------
// f32x2 packed helpers (Blackwell dual-fp32 pipe)
// ---------------------------------------------------------------------------
__device__ __forceinline__ u64 pack2(float v) {
    u64 r; asm("mov.b64 %0, {%1, %1};" : "=l"(r) : "f"(v)); return r;
}
__device__ __forceinline__ u64 fma2(u64 a, u64 b, u64 c) {
    u64 d; asm("fma.rn.f32x2 %0, %1, %2, %3;" : "=l"(d) : "l"(a), "l"(b), "l"(c));
    return d;
}

// ---------------------------------------------------------------------------
// Kernel 1: detect whether group_id is int64 (hi words all zero) or int32
// ---------------------------------------------------------------------------
__global__ void detect_kernel(const unsigned int* __restrict__ raw) {
    unsigned int acc = 0;
    for (int i = threadIdx.x; i < BT_ / 2; i += 256) acc |= raw[2 * i + 1];
    #pragma unroll
    for (int o = 16; o; o >>= 1) acc |= __shfl_xor_sync(0xffffffffu, acc, o);
    __shared__ unsigned int s[8];
    if ((threadIdx.x & 31) == 0) s[threadIdx.x >> 5] = acc;
    __syncthreads();
    if (threadIdx.x == 0) {
        unsigned int t = 0;
        #pragma unroll
        for (int i = 0; i < 8; i++) t |= s[i];
        g_is64 = (t == 0) ? 1 : 0;
    }
}

// Kernel 2: normalize group ids to int32
__global__ void convert_kernel(const unsigned int* __restrict__ raw) {
    int t = blockIdx.x * 256 + threadIdx.x;
    if (t < BT_) {
        int v = g_is64 ? (int)raw[2 * t] : (int)raw[t];
        g_gid[t] = v;
    }
}

// ---------------------------------------------------------------------------
// Kernel 3/4: qk[d] = sum_e query[e] * Wk[e,d], then *= norm_w[d]
// ---------------------------------------------------------------------------
__global__ void __launch_bounds__(128) qk_part_kernel(
    const float* __restrict__ query, const float* __restrict__ Wk) {
    int d  = blockIdx.x * 128 + threadIdx.x;   // 8 blocks in x
    int e0 = blockIdx.y * 64;                  // 16 splits in y
    float s = 0.f;
    #pragma unroll 8
    for (int e = e0; e < e0 + 64; e++) s += query[e] * Wk[(size_t)e * D_ + d];
    g_qk_part[blockIdx.y * D_ + d] = s;
}

__global__ void __launch_bounds__(128) qk_finish_kernel(const float* __restrict__ norm_w) {
    int d = blockIdx.x * 128 + threadIdx.x;
    float s = 0.f;
    #pragma unroll
    for (int p = 0; p < 16; p++) s += g_qk_part[p * D_ + d];
    g_qkd[d] = s * norm_w[d];
}

// ---------------------------------------------------------------------------
// Kernel 5: per-token stats — sum(x^2) and x . qkd  (one 128-thr block/token)
// ---------------------------------------------------------------------------
__global__ void __launch_bounds__(128) token_stats_kernel(const float* __restrict__ x) {
    int tok = blockIdx.x;
    int tid = threadIdx.x;
    const float4* xt = (const float4*)(x + (size_t)tok * D_);
    const float4* qk = (const float4*)g_qkd;
    float ss = 0.f, dq = 0.f;
    #pragma unroll
    for (int r = 0; r < 2; r++) {
        int i = r * 128 + tid;
        float4 v = xt[i];
        float4 q = qk[i];
        ss += v.x * v.x + v.y * v.y + v.z * v.z + v.w * v.w;
        dq += v.x * q.x + v.y * q.y + v.z * q.z + v.w * q.w;
    }
    #pragma unroll
    for (int o = 16; o; o >>= 1) {
        ss += __shfl_xor_sync(0xffffffffu, ss, o);
        dq += __shfl_xor_sync(0xffffffffu, dq, o);
    }
    __shared__ float sS[4], sD[4];
    if ((tid & 31) == 0) { sS[tid >> 5] = ss; sD[tid >> 5] = dq; }
    __syncthreads();
    if (tid == 0) {
        float S = sS[0] + sS[1] + sS[2] + sS[3];
        float Q = sD[0] + sD[1] + sD[2] + sD[3];
        float ir = rsqrtf(S * (1.0f / (float)D_) + EPS_);
        g_invrms[tok] = ir;
        g_score[tok]  = Q * ir * INV_SQRT_D_;
    }
}

// ---------------------------------------------------------------------------
// Kernel 6: segment softmax stats per (b,g): max and 1/denom
// ---------------------------------------------------------------------------
__global__ void __launch_bounds__(128) seg_softmax_kernel() {
    int b = blockIdx.x >> 6;
    int g = blockIdx.x & 63;
    int tid = threadIdx.x;
    const float* sc  = g_score + b * T_;
    const int*   gid = g_gid   + b * T_;

    float mx = -3.402823466e38f;
    for (int t = tid; t < T_; t += 128)
        if (gid[t] == g) mx = fmaxf(mx, sc[t]);
    #pragma unroll
    for (int o = 16; o; o >>= 1) mx = fmaxf(mx, __shfl_xor_sync(0xffffffffu, mx, o));
    __shared__ float sm[4];
    if ((tid & 31) == 0) sm[tid >> 5] = mx;
    __syncthreads();
    mx = fmaxf(fmaxf(sm[0], sm[1]), fmaxf(sm[2], sm[3]));  // broadcast to all

    float sum = 0.f;
    for (int t = tid; t < T_; t += 128)
        if (gid[t] == g) sum += __expf(sc[t] - mx);
    #pragma unroll
    for (int o = 16; o; o >>= 1) sum += __shfl_xor_sync(0xffffffffu, sum, o);
    __shared__ float ssum[4];
    if ((tid & 31) == 0) ssum[tid >> 5] = sum;
    __syncthreads();
    if (tid == 0) {
        float S = ssum[0] + ssum[1] + ssum[2] + ssum[3];
        g_m[blockIdx.x]    = (mx > -1e37f) ? mx : 0.f;
        g_rden[blockIdx.x] = (S > 0.f) ? (1.0f / S) : 0.f;
    }
}

// ---------------------------------------------------------------------------
// Kernel 7: per-token coefficient  coef = exp(s - m[g]) / denom * invrms
// ---------------------------------------------------------------------------
__global__ void coef_kernel() {
    int t = blockIdx.x * 256 + threadIdx.x;
    if (t < BT_) {
        int b  = t >> 12;
        int g  = g_gid[t];
        int bg = b * G_ + g;
        float c = __expf(g_score[t] - g_m[bg]) * g_rden[bg] * g_invrms[t];
        g_wg[t] = make_float2(c, __int_as_float(g));
    }
}

// ---------------------------------------------------------------------------
// Kernel 8: group pooling  p[b,g,d] = sum_t coef * x[b,t,d], *norm_w at flush.
// v2: 16-token unroll per warp => 16 front-batched LDG.32 per warp (2KB/warp
// in flight) + 64KB smem (2 CTAs/SM) => ~16KB/SM in flight, full HBM BW.
// smem acc layout: [4 warps][2 parity][64 groups * 32 cols]  = 64 KB.
// Deterministic: each (warp, parity, g, col) slot owned by one thread;
// flush sums the 8 copies in fixed order.
// ---------------------------------------------------------------------------
__global__ void __launch_bounds__(128) pool_kernel(
    const float* __restrict__ x, const float* __restrict__ norm_w) {
    extern __shared__ float acc[];   // 4 * 2 * 2048 floats = 64 KB
    int tid  = threadIdx.x;
    int lane = tid & 31;
    int w    = tid >> 5;
    int ch   = blockIdx.x;           // 0..31 (column chunk of 32)
    int b    = blockIdx.y;           // 0..7

    for (int i = tid; i < 4 * 2 * 2048; i += 128) acc[i] = 0.f;
    __syncthreads();

    float* aw = acc + w * 4096;                   // this warp's 2 parity buffers
    const float2* wg = g_wg + b * T_;
    const float*  xb = x + (size_t)b * T_ * D_ + (size_t)ch * 32 + lane;

    for (int i = 0; i < T_ / 64; i++) {           // 64 iterations
        int t0 = i * 64 + w * 16;                 // 16 consecutive tokens / warp
        float2 ws[16];
        float  xs[16];
        #pragma unroll
        for (int k = 0; k < 16; k++) ws[k] = wg[t0 + k];
        #pragma unroll
        for (int k = 0; k < 16; k++) xs[k] = xb[(size_t)(t0 + k) * D_];
        #pragma unroll
        for (int k = 0; k < 16; k++) {
            int idx = __float_as_int(ws[k].y) * 32 + lane + (k & 1) * 2048;
            aw[idx] = fmaf(ws[k].x, xs[k], aw[idx]);
        }
    }
    __syncthreads();

    // Flush: sum 8 buffers per (g, col), apply norm_w, write p.
    float* pout = g_p + (size_t)b * G_ * D_ + (size_t)ch * 32;
    for (int i = tid; i < G_ * 32; i += 128) {
        int g = i >> 5, c = i & 31;
        float s = 0.f;
        #pragma unroll
        for (int ww = 0; ww < 4; ww++)
            #pragma unroll
            for (int q = 0; q < 2; q++)
                s += acc[ww * 4096 + q * 2048 + g * 32 + c];
        pout[(size_t)g * D_ + c] = s * norm_w[ch * 32 + c];
    }
}

// ---------------------------------------------------------------------------
// Kernel 9: out = p @ Wv^T, split-K=4.  M=512, N=1024, K=1024.
// 128x128 tiles, BK=8, 256 threads, 8x8 microtiles via packed f32x2 FMA.
// b-pairs are read bit-identically as 64-bit words straight from smem;
// a is duplicated with one mov.b64 (alu pipe, hidden under fma pipe).
// ---------------------------------------------------------------------------
__global__ void __launch_bounds__(256) gemm_kernel(const float* __restrict__ Wv) {
    __shared__ float As[8][128];
    __shared__ float Bs[8][128];
    int tid = threadIdx.x;
    int bn = blockIdx.x, bm = blockIdx.y, ks = blockIdx.z;
    int row = tid >> 1;            // 0..127 (loader row)
    int kq  = (tid & 1) * 4;       // loader k quad
    int tx = tid & 15, ty = tid >> 4;

    const float* Ag = g_p + (size_t)(bm * 128 + row) * D_ + ks * 256 + kq;
    const float* Bg = Wv  + (size_t)(bn * 128 + row) * D_ + ks * 256 + kq;

    u64 acc2[8][4];
    #pragma unroll
    for (int r = 0; r < 8; r++)
        #pragma unroll
        for (int c = 0; c < 4; c++) acc2[r][c] = 0ull;

    for (int k0 = 0; k0 < 256; k0 += 8) {
        float4 av = *(const float4*)(Ag + k0);
        float4 bv = *(const float4*)(Bg + k0);
        __syncthreads();
        As[kq + 0][row] = av.x; As[kq + 1][row] = av.y;
        As[kq + 2][row] = av.z; As[kq + 3][row] = av.w;
        Bs[kq + 0][row] = bv.x; Bs[kq + 1][row] = bv.y;
        Bs[kq + 2][row] = bv.z; Bs[kq + 3][row] = bv.w;
        __syncthreads();
        #pragma unroll
        for (int kk = 0; kk < 8; kk++) {
            float4 a0 = *(const float4*)&As[kk][ty * 8];
            float4 a1 = *(const float4*)&As[kk][ty * 8 + 4];
            ulonglong2 bb0 = *(const ulonglong2*)&Bs[kk][tx * 8];
            ulonglong2 bb1 = *(const ulonglong2*)&Bs[kk][tx * 8 + 4];
            u64 bc[4] = {bb0.x, bb0.y, bb1.x, bb1.y};
            float a[8] = {a0.x, a0.y, a0.z, a0.w, a1.x, a1.y, a1.z, a1.w};
            #pragma unroll
            for (int r = 0; r < 8; r++) {
                u64 ar = pack2(a[r]);
                #pragma unroll
                for (int c = 0; c < 4; c++)
                    acc2[r][c] = fma2(ar, bc[c], acc2[r][c]);
            }
        }
    }

    float* op = g_out_part[ks] + (size_t)(bm * 128 + ty * 8) * D_ + bn * 128 + tx * 8;
    #pragma unroll
    for (int r = 0; r < 8; r++) {
        // packed u64 pairs are bit-identical to two consecutive floats
        *(ulonglong2*)(op + (size_t)r * D_)     = make_ulonglong2(acc2[r][0], acc2[r][1]);
        *(ulonglong2*)(op + (size_t)r * D_ + 4) = make_ulonglong2(acc2[r][2], acc2[r][3]);
    }
}

// Kernel 10: fixed-order split-K reduction into d_out
__global__ void gemm_reduce_kernel(float* __restrict__ out) {
    int idx = blockIdx.x * 256 + threadIdx.x;
    if (idx < BG_ * D_) {
        float s = g_out_part[0][idx] + g_out_part[1][idx]
                + g_out_part[2][idx] + g_out_part[3][idx];
        out[idx] = s;
    }
}

// ---------------------------------------------------------------------------
// Launch
// ---------------------------------------------------------------------------
extern "C" void kernel_launch(void* const* d_in, const int* in_sizes, int n_in,
                              void* d_out, int out_size) {
    const float* x = nullptr;
    const void*  gid = nullptr;
    const float* query = nullptr;
    const float* norm_w = nullptr;
    const float* Wk = nullptr;
    const float* Wv = nullptr;

    for (int i = 0; i < n_in; i++) {
        int s = in_sizes[i];
        if (s == B_ * T_ * D_)      x = (const float*)d_in[i];
        else if (s == BT_)          gid = d_in[i];
        else if (s == D_) {
            if (!query) query = (const float*)d_in[i];
            else        norm_w = (const float*)d_in[i];
        } else if (s == D_ * D_) {
            if (!Wk) Wk = (const float*)d_in[i];
            else     Wv = (const float*)d_in[i];
        }
    }
    if (!x || !gid || !query || !norm_w || !Wk || !Wv) return;

    float* out = (float*)d_out;
    (void)out_size;

    cudaFuncSetAttribute(pool_kernel,
                         cudaFuncAttributeMaxDynamicSharedMemorySize, 65536);

    detect_kernel<<<1, 256>>>((const unsigned int*)gid);
    convert_kernel<<<(BT_ + 255) / 256, 256>>>((const unsigned int*)gid);
    qk_part_kernel<<<dim3(8, 16), 128>>>(query, Wk);
    qk_finish_kernel<<<8, 128>>>(norm_w);
    token_stats_kernel<<<BT_, 128>>>(x);
    seg_softmax_kernel<<<BG_, 128>>>();
    coef_kernel<<<(BT_ + 255) / 256, 256>>>();
    pool_kernel<<<dim3(32, 8), 128, 65536>>>(x, norm_w);
    gemm_kernel<<<dim3(8, 4, 4), 256>>>(Wv);
    gemm_reduce_kernel<<<(BG_ * D_ + 255) / 256, 256>>>(out);
}

// round 4
// speedup vs baseline: 1.8307x; 1.0741x over previous
#include <cuda_runtime.h>
#include <cstdint>
#include <cstddef>

// Problem constants (AttentionPool: B=8, T=4096, D=1024, G=64)
#define B_  8
#define T_  4096
#define D_  1024
#define G_  64
#define BT_ (B_ * T_)           // 32768 tokens
#define BG_ (B_ * G_)           // 512 (b,g) pairs
#define EPS_ 1.1920928955078125e-07f   // finfo(float32).eps
#define INV_SQRT_D_ (1.0f / 32.0f)

typedef unsigned long long u64;

// ---------------------------------------------------------------------------
// Device scratch (static — no allocations allowed)
// ---------------------------------------------------------------------------
__device__ float  g_qk_part[16 * D_];       // partial Wk^T q
__device__ float  g_qkd[D_];                // norm_w * (Wk^T q)
__device__ float  g_score[BT_];             // per-token score
__device__ float  g_invrms[BT_];            // per-token 1/rms
__device__ int    g_is64;                   // group_id dtype flag
__device__ float2 g_wg[BT_];                // {coef, group_as_bits} per token
__device__ float  g_p2[2][BG_ * D_];        // pooled h partials (token split)
__device__ float  g_out_part[4][BG_ * D_];  // split-K GEMM partials

// ---------------------------------------------------------------------------
// f32x2 packed helpers (Blackwell dual-fp32 pipe)
// ---------------------------------------------------------------------------
__device__ __forceinline__ u64 pack2(float v) {
    u64 r; asm("mov.b64 %0, {%1, %1};" : "=l"(r) : "f"(v)); return r;
}
__device__ __forceinline__ u64 fma2(u64 a, u64 b, u64 c) {
    u64 d; asm("fma.rn.f32x2 %0, %1, %2, %3;" : "=l"(d) : "l"(a), "l"(b), "l"(c));
    return d;
}

// ---------------------------------------------------------------------------
// Kernel: qk partials  qk[d] = sum_e query[e] * Wk[e,d]
// ---------------------------------------------------------------------------
__global__ void __launch_bounds__(128) qk_part_kernel(
    const float* __restrict__ query, const float* __restrict__ Wk) {
    int d  = blockIdx.x * 128 + threadIdx.x;   // 8 blocks in x
    int e0 = blockIdx.y * 64;                  // 16 splits in y
    float s = 0.f;
    #pragma unroll 8
    for (int e = e0; e < e0 + 64; e++) s += query[e] * Wk[(size_t)e * D_ + d];
    g_qk_part[blockIdx.y * D_ + d] = s;
}

__global__ void __launch_bounds__(128) qk_finish_kernel(const float* __restrict__ norm_w) {
    int d = blockIdx.x * 128 + threadIdx.x;
    float s = 0.f;
    #pragma unroll
    for (int p = 0; p < 16; p++) s += g_qk_part[p * D_ + d];
    g_qkd[d] = s * norm_w[d];
}

// ---------------------------------------------------------------------------
// Kernel: per-token stats, warp-per-token. 8 warps/block, no barriers.
// 16 front-batched LDG.128 per lane => MLP 16, BW-bound.
// ---------------------------------------------------------------------------
__global__ void __launch_bounds__(256) token_stats_kernel(const float* __restrict__ x) {
    int tok  = blockIdx.x * 8 + (threadIdx.x >> 5);
    int lane = threadIdx.x & 31;
    const float4* xt = (const float4*)(x + (size_t)tok * D_);
    const float4* qk = (const float4*)g_qkd;

    float4 xv[8], qv[8];
    #pragma unroll
    for (int r = 0; r < 8; r++) xv[r] = xt[r * 32 + lane];
    #pragma unroll
    for (int r = 0; r < 8; r++) qv[r] = qk[r * 32 + lane];

    float ss = 0.f, dq = 0.f;
    #pragma unroll
    for (int r = 0; r < 8; r++) {
        float4 v = xv[r], q = qv[r];
        ss += v.x * v.x + v.y * v.y + v.z * v.z + v.w * v.w;
        dq += v.x * q.x + v.y * q.y + v.z * q.z + v.w * q.w;
    }
    #pragma unroll
    for (int o = 16; o; o >>= 1) {
        ss += __shfl_xor_sync(0xffffffffu, ss, o);
        dq += __shfl_xor_sync(0xffffffffu, dq, o);
    }
    if (lane == 0) {
        float ir = rsqrtf(ss * (1.0f / (float)D_) + EPS_);
        g_invrms[tok] = ir;
        g_score[tok]  = dq * ir * INV_SQRT_D_;
    }
}

// ---------------------------------------------------------------------------
// Kernel: detect whether group_id is int64 (hi words all zero) or int32
// ---------------------------------------------------------------------------
__global__ void detect_kernel(const unsigned int* __restrict__ raw) {
    unsigned int acc = 0;
    for (int i = threadIdx.x; i < BT_ / 2; i += 256) acc |= raw[2 * i + 1];
    #pragma unroll
    for (int o = 16; o; o >>= 1) acc |= __shfl_xor_sync(0xffffffffu, acc, o);
    __shared__ unsigned int s[8];
    if ((threadIdx.x & 31) == 0) s[threadIdx.x >> 5] = acc;
    __syncthreads();
    if (threadIdx.x == 0) {
        unsigned int t = 0;
        #pragma unroll
        for (int i = 0; i < 8; i++) t |= s[i];
        g_is64 = (t == 0) ? 1 : 0;
    }
}

// ---------------------------------------------------------------------------
// Kernel: segment softmax per (b,g) FUSED with per-token coef write.
// coef = exp(s - m) / denom * invrms, stored with group id as float2.
// ---------------------------------------------------------------------------
__global__ void __launch_bounds__(128) seg_softmax_kernel(const unsigned int* __restrict__ raw) {
    int b = blockIdx.x >> 6;
    int g = blockIdx.x & 63;
    int tid = threadIdx.x;
    int is64 = g_is64;
    const float* sc = g_score + b * T_;
    int base = b * T_;

    // Pass 1: max over this group's tokens
    float mx = -3.402823466e38f;
    for (int t = tid; t < T_; t += 128) {
        int gid = (int)(is64 ? raw[2 * (base + t)] : raw[base + t]);
        if (gid == g) mx = fmaxf(mx, sc[t]);
    }
    #pragma unroll
    for (int o = 16; o; o >>= 1) mx = fmaxf(mx, __shfl_xor_sync(0xffffffffu, mx, o));
    __shared__ float sm[4];
    if ((tid & 31) == 0) sm[tid >> 5] = mx;
    __syncthreads();
    mx = fmaxf(fmaxf(sm[0], sm[1]), fmaxf(sm[2], sm[3]));
    if (mx < -1e37f) mx = 0.f;   // empty group guard

    // Pass 2: sum of exp
    float sum = 0.f;
    for (int t = tid; t < T_; t += 128) {
        int gid = (int)(is64 ? raw[2 * (base + t)] : raw[base + t]);
        if (gid == g) sum += __expf(sc[t] - mx);
    }
    #pragma unroll
    for (int o = 16; o; o >>= 1) sum += __shfl_xor_sync(0xffffffffu, sum, o);
    __shared__ float ssum[4];
    if ((tid & 31) == 0) ssum[tid >> 5] = sum;
    __syncthreads();
    float S = ssum[0] + ssum[1] + ssum[2] + ssum[3];
    float rden = (S > 0.f) ? (1.0f / S) : 0.f;

    // Pass 3: write per-token coefficients for this group's tokens
    float gb = __int_as_float(g);
    for (int t = tid; t < T_; t += 128) {
        int gid = (int)(is64 ? raw[2 * (base + t)] : raw[base + t]);
        if (gid == g) {
            float c = __expf(sc[t] - mx) * rden * g_invrms[base + t];
            g_wg[base + t] = make_float2(c, gb);
        }
    }
}

// ---------------------------------------------------------------------------
// Kernel: group pooling  p[b,g,d] += coef * x[b,t,d], *norm_w at flush.
// Grid (32 col-chunks, 8 batches, 2 token-splits) = 512 CTAs (~3/SM).
// 16-token front-batched LDGs per warp; per-warp x 2-parity smem accs (64KB).
// ---------------------------------------------------------------------------
__global__ void __launch_bounds__(128) pool_kernel(
    const float* __restrict__ x, const float* __restrict__ norm_w) {
    extern __shared__ float acc[];   // 4 * 2 * 2048 floats = 64 KB
    int tid  = threadIdx.x;
    int lane = tid & 31;
    int w    = tid >> 5;
    int ch   = blockIdx.x;           // 0..31 (column chunk of 32)
    int b    = blockIdx.y;           // 0..7
    int z    = blockIdx.z;           // 0..1 (token split)

    for (int i = tid; i < 4 * 2 * 2048; i += 128) acc[i] = 0.f;
    __syncthreads();

    float* aw = acc + w * 4096;
    const float2* wg = g_wg + b * T_;
    const float*  xb = x + (size_t)b * T_ * D_ + (size_t)ch * 32 + lane;

    for (int i = z * 32; i < z * 32 + 32; i++) {   // 32 iterations per split
        int t0 = i * 64 + w * 16;
        float2 ws[16];
        float  xs[16];
        #pragma unroll
        for (int k = 0; k < 16; k++) ws[k] = wg[t0 + k];
        #pragma unroll
        for (int k = 0; k < 16; k++) xs[k] = xb[(size_t)(t0 + k) * D_];
        #pragma unroll
        for (int k = 0; k < 16; k++) {
            int idx = __float_as_int(ws[k].y) * 32 + lane + (k & 1) * 2048;
            aw[idx] = fmaf(ws[k].x, xs[k], aw[idx]);
        }
    }
    __syncthreads();

    // Flush: sum 8 buffers per (g, col), apply norm_w, write partial p.
    float* pout = g_p2[z] + (size_t)b * G_ * D_ + (size_t)ch * 32;
    for (int i = tid; i < G_ * 32; i += 128) {
        int g = i >> 5, c = i & 31;
        float s = 0.f;
        #pragma unroll
        for (int ww = 0; ww < 4; ww++)
            #pragma unroll
            for (int q = 0; q < 2; q++)
                s += acc[ww * 4096 + q * 2048 + g * 32 + c];
        pout[(size_t)g * D_ + c] = s * norm_w[ch * 32 + c];
    }
}

// ---------------------------------------------------------------------------
// Kernel: out = p @ Wv^T, split-K=4.  M=512, N=1024, K=1024.
// A is read as p2[0] + p2[1] (token-split partial sum folded into load).
// 128x128 tiles, BK=8, 256 threads, 8x8 microtiles via packed f32x2 FMA.
// ---------------------------------------------------------------------------
__global__ void __launch_bounds__(256) gemm_kernel(const float* __restrict__ Wv) {
    __shared__ float As[8][128];
    __shared__ float Bs[8][128];
    int tid = threadIdx.x;
    int bn = blockIdx.x, bm = blockIdx.y, ks = blockIdx.z;
    int row = tid >> 1;            // 0..127 (loader row)
    int kq  = (tid & 1) * 4;       // loader k quad
    int tx = tid & 15, ty = tid >> 4;

    size_t aoff = (size_t)(bm * 128 + row) * D_ + ks * 256 + kq;
    const float* Ag0 = g_p2[0] + aoff;
    const float* Ag1 = g_p2[1] + aoff;
    const float* Bg  = Wv + (size_t)(bn * 128 + row) * D_ + ks * 256 + kq;

    u64 acc2[8][4];
    #pragma unroll
    for (int r = 0; r < 8; r++)
        #pragma unroll
        for (int c = 0; c < 4; c++) acc2[r][c] = 0ull;

    for (int k0 = 0; k0 < 256; k0 += 8) {
        float4 a0v = *(const float4*)(Ag0 + k0);
        float4 a1v = *(const float4*)(Ag1 + k0);
        float4 bv  = *(const float4*)(Bg + k0);
        float4 av  = make_float4(a0v.x + a1v.x, a0v.y + a1v.y,
                                 a0v.z + a1v.z, a0v.w + a1v.w);
        __syncthreads();
        As[kq + 0][row] = av.x; As[kq + 1][row] = av.y;
        As[kq + 2][row] = av.z; As[kq + 3][row] = av.w;
        Bs[kq + 0][row] = bv.x; Bs[kq + 1][row] = bv.y;
        Bs[kq + 2][row] = bv.z; Bs[kq + 3][row] = bv.w;
        __syncthreads();
        #pragma unroll
        for (int kk = 0; kk < 8; kk++) {
            float4 a0 = *(const float4*)&As[kk][ty * 8];
            float4 a1 = *(const float4*)&As[kk][ty * 8 + 4];
            ulonglong2 bb0 = *(const ulonglong2*)&Bs[kk][tx * 8];
            ulonglong2 bb1 = *(const ulonglong2*)&Bs[kk][tx * 8 + 4];
            u64 bc[4] = {bb0.x, bb0.y, bb1.x, bb1.y};
            float a[8] = {a0.x, a0.y, a0.z, a0.w, a1.x, a1.y, a1.z, a1.w};
            #pragma unroll
            for (int r = 0; r < 8; r++) {
                u64 ar = pack2(a[r]);
                #pragma unroll
                for (int c = 0; c < 4; c++)
                    acc2[r][c] = fma2(ar, bc[c], acc2[r][c]);
            }
        }
    }

    float* op = g_out_part[ks] + (size_t)(bm * 128 + ty * 8) * D_ + bn * 128 + tx * 8;
    #pragma unroll
    for (int r = 0; r < 8; r++) {
        *(ulonglong2*)(op + (size_t)r * D_)     = make_ulonglong2(acc2[r][0], acc2[r][1]);
        *(ulonglong2*)(op + (size_t)r * D_ + 4) = make_ulonglong2(acc2[r][2], acc2[r][3]);
    }
}

// Kernel: fixed-order split-K reduction into d_out
__global__ void gemm_reduce_kernel(float* __restrict__ out) {
    int idx = blockIdx.x * 256 + threadIdx.x;
    if (idx < BG_ * D_) {
        float s = g_out_part[0][idx] + g_out_part[1][idx]
                + g_out_part[2][idx] + g_out_part[3][idx];
        out[idx] = s;
    }
}

// ---------------------------------------------------------------------------
// Launch (8 launches; pool lands at 0-based index 5 for ncu -s 5)
// ---------------------------------------------------------------------------
extern "C" void kernel_launch(void* const* d_in, const int* in_sizes, int n_in,
                              void* d_out, int out_size) {
    const float* x = nullptr;
    const void*  gid = nullptr;
    const float* query = nullptr;
    const float* norm_w = nullptr;
    const float* Wk = nullptr;
    const float* Wv = nullptr;

    for (int i = 0; i < n_in; i++) {
        int s = in_sizes[i];
        if (s == B_ * T_ * D_)      x = (const float*)d_in[i];
        else if (s == BT_)          gid = d_in[i];
        else if (s == D_) {
            if (!query) query = (const float*)d_in[i];
            else        norm_w = (const float*)d_in[i];
        } else if (s == D_ * D_) {
            if (!Wk) Wk = (const float*)d_in[i];
            else     Wv = (const float*)d_in[i];
        }
    }
    if (!x || !gid || !query || !norm_w || !Wk || !Wv) return;

    float* out = (float*)d_out;
    (void)out_size;

    cudaFuncSetAttribute(pool_kernel,
                         cudaFuncAttributeMaxDynamicSharedMemorySize, 65536);

    qk_part_kernel<<<dim3(8, 16), 128>>>(query, Wk);           // 0
    qk_finish_kernel<<<8, 128>>>(norm_w);                      // 1
    token_stats_kernel<<<BT_ / 8, 256>>>(x);                   // 2
    detect_kernel<<<1, 256>>>((const unsigned int*)gid);       // 3
    seg_softmax_kernel<<<BG_, 128>>>((const unsigned int*)gid);// 4
    pool_kernel<<<dim3(32, 8, 2), 128, 65536>>>(x, norm_w);    // 5  <- ncu -s 5
    gemm_kernel<<<dim3(8, 4, 4), 256>>>(Wv);                   // 6
    gemm_reduce_kernel<<<(BG_ * D_ + 255) / 256, 256>>>(out);  // 7
}

// round 5
// speedup vs baseline: 1.8843x; 1.0293x over previous
#include <cuda_runtime.h>
#include <cstdint>
#include <cstddef>

// Problem constants (AttentionPool: B=8, T=4096, D=1024, G=64)
#define B_  8
#define T_  4096
#define D_  1024
#define G_  64
#define BT_ (B_ * T_)           // 32768 tokens
#define BG_ (B_ * G_)           // 512 (b,g) pairs
#define EPS_ 1.1920928955078125e-07f   // finfo(float32).eps
#define INV_SQRT_D_ (1.0f / 32.0f)

typedef unsigned long long u64;

// ---------------------------------------------------------------------------
// Device scratch (static — no allocations allowed)
// ---------------------------------------------------------------------------
__device__ float  g_qkd[D_];                // norm_w * (Wk^T q)
__device__ float  g_score[BT_];             // per-token score
__device__ float  g_invrms[BT_];            // per-token 1/rms
__device__ float2 g_wg[BT_];                // {coef, group_as_bits} per token
__device__ float  g_p2[2][BG_ * D_];        // pooled h partials (token split)
__device__ float  g_out_part[4][BG_ * D_];  // split-K GEMM partials

// ---------------------------------------------------------------------------
// f32x2 packed helpers (Blackwell dual-fp32 pipe)
// ---------------------------------------------------------------------------
__device__ __forceinline__ u64 pack2(float v) {
    u64 r; asm("mov.b64 %0, {%1, %1};" : "=l"(r) : "f"(v)); return r;
}
__device__ __forceinline__ u64 fma2(u64 a, u64 b, u64 c) {
    u64 d; asm("fma.rn.f32x2 %0, %1, %2, %3;" : "=l"(d) : "l"(a), "l"(b), "l"(c));
    return d;
}

// ---------------------------------------------------------------------------
// Kernel 0: fused qk GEMV  qkd[d] = norm_w[d] * sum_e query[e] * Wk[e,d]
// Grid 64 x 256 threads: 16 d-cols per block, 16-way e-split, smem reduce.
// ---------------------------------------------------------------------------
__global__ void __launch_bounds__(256) qk_kernel(
    const float* __restrict__ query, const float* __restrict__ Wk,
    const float* __restrict__ norm_w) {
    int di = threadIdx.x & 15;
    int eg = threadIdx.x >> 4;
    int d  = blockIdx.x * 16 + di;
    float s = 0.f;
    #pragma unroll 8
    for (int e = eg; e < D_; e += 16) s += query[e] * Wk[(size_t)e * D_ + d];
    __shared__ float red[16][17];
    red[eg][di] = s;
    __syncthreads();
    if (threadIdx.x < 16) {
        int dd = blockIdx.x * 16 + threadIdx.x;
        float t = 0.f;
        #pragma unroll
        for (int i = 0; i < 16; i++) t += red[i][threadIdx.x];
        g_qkd[dd] = t * norm_w[dd];
    }
}

// ---------------------------------------------------------------------------
// Kernel 1: per-token stats, warp-per-token. 8 warps/block, no barriers.
// ---------------------------------------------------------------------------
__global__ void __launch_bounds__(256) token_stats_kernel(const float* __restrict__ x) {
    int tok  = blockIdx.x * 8 + (threadIdx.x >> 5);
    int lane = threadIdx.x & 31;
    const float4* xt = (const float4*)(x + (size_t)tok * D_);
    const float4* qk = (const float4*)g_qkd;

    float4 xv[8], qv[8];
    #pragma unroll
    for (int r = 0; r < 8; r++) xv[r] = xt[r * 32 + lane];
    #pragma unroll
    for (int r = 0; r < 8; r++) qv[r] = qk[r * 32 + lane];

    float ss = 0.f, dq = 0.f;
    #pragma unroll
    for (int r = 0; r < 8; r++) {
        float4 v = xv[r], q = qv[r];
        ss += v.x * v.x + v.y * v.y + v.z * v.z + v.w * v.w;
        dq += v.x * q.x + v.y * q.y + v.z * q.z + v.w * q.w;
    }
    #pragma unroll
    for (int o = 16; o; o >>= 1) {
        ss += __shfl_xor_sync(0xffffffffu, ss, o);
        dq += __shfl_xor_sync(0xffffffffu, dq, o);
    }
    if (lane == 0) {
        float ir = rsqrtf(ss * (1.0f / (float)D_) + EPS_);
        g_invrms[tok] = ir;
        g_score[tok]  = dq * ir * INV_SQRT_D_;
    }
}

// ---------------------------------------------------------------------------
// Kernel 2: segment softmax per (b,g) + per-token coef write.
// Inline dtype detect: OR of raw[2t+1], t<128 (<=1KB — in bounds for both
// int32 and int64 layouts; OR==0 means the interpretations coincide anyway).
// ---------------------------------------------------------------------------
__global__ void __launch_bounds__(128) seg_softmax_kernel(const unsigned int* __restrict__ raw) {
    int b = blockIdx.x >> 6;
    int g = blockIdx.x & 63;
    int tid = threadIdx.x;

    // inline is64 detection
    unsigned int det = raw[2 * tid + 1];
    #pragma unroll
    for (int o = 16; o; o >>= 1) det |= __shfl_xor_sync(0xffffffffu, det, o);
    __shared__ unsigned int sdet[4];
    if ((tid & 31) == 0) sdet[tid >> 5] = det;
    __syncthreads();
    int is64 = ((sdet[0] | sdet[1] | sdet[2] | sdet[3]) == 0) ? 1 : 0;

    const float* sc = g_score + b * T_;
    int base = b * T_;

    // Pass 1: max over this group's tokens
    float mx = -3.402823466e38f;
    for (int t = tid; t < T_; t += 128) {
        int gid = (int)(is64 ? raw[2 * (base + t)] : raw[base + t]);
        if (gid == g) mx = fmaxf(mx, sc[t]);
    }
    #pragma unroll
    for (int o = 16; o; o >>= 1) mx = fmaxf(mx, __shfl_xor_sync(0xffffffffu, mx, o));
    __shared__ float sm[4];
    if ((tid & 31) == 0) sm[tid >> 5] = mx;
    __syncthreads();
    mx = fmaxf(fmaxf(sm[0], sm[1]), fmaxf(sm[2], sm[3]));
    if (mx < -1e37f) mx = 0.f;   // empty group guard

    // Pass 2: sum of exp
    float sum = 0.f;
    for (int t = tid; t < T_; t += 128) {
        int gid = (int)(is64 ? raw[2 * (base + t)] : raw[base + t]);
        if (gid == g) sum += __expf(sc[t] - mx);
    }
    #pragma unroll
    for (int o = 16; o; o >>= 1) sum += __shfl_xor_sync(0xffffffffu, sum, o);
    __shared__ float ssum[4];
    if ((tid & 31) == 0) ssum[tid >> 5] = sum;
    __syncthreads();
    float S = ssum[0] + ssum[1] + ssum[2] + ssum[3];
    float rden = (S > 0.f) ? (1.0f / S) : 0.f;

    // Pass 3: write per-token coefficients for this group's tokens
    float gb = __int_as_float(g);
    for (int t = tid; t < T_; t += 128) {
        int gid = (int)(is64 ? raw[2 * (base + t)] : raw[base + t]);
        if (gid == g) {
            float c = __expf(sc[t] - mx) * rden * g_invrms[base + t];
            g_wg[base + t] = make_float2(c, gb);
        }
    }
}

// ---------------------------------------------------------------------------
// Kernel 3: group pooling  p[b,g,d] += coef * x[b,t,d], *norm_w at flush.
// Grid (32 col-chunks, 8 batches, 2 token-splits) = 512 CTAs.
// 16-token front-batched LDGs per warp; per-warp x 2-parity smem accs (64KB).
// ---------------------------------------------------------------------------
__global__ void __launch_bounds__(128) pool_kernel(
    const float* __restrict__ x, const float* __restrict__ norm_w) {
    extern __shared__ float acc[];   // 4 * 2 * 2048 floats = 64 KB
    int tid  = threadIdx.x;
    int lane = tid & 31;
    int w    = tid >> 5;
    int ch   = blockIdx.x;           // 0..31 (column chunk of 32)
    int b    = blockIdx.y;           // 0..7
    int z    = blockIdx.z;           // 0..1 (token split)

    for (int i = tid; i < 4 * 2 * 2048; i += 128) acc[i] = 0.f;
    __syncthreads();

    float* aw = acc + w * 4096;
    const float2* wg = g_wg + b * T_;
    const float*  xb = x + (size_t)b * T_ * D_ + (size_t)ch * 32 + lane;

    for (int i = z * 32; i < z * 32 + 32; i++) {   // 32 iterations per split
        int t0 = i * 64 + w * 16;
        float2 ws[16];
        float  xs[16];
        #pragma unroll
        for (int k = 0; k < 16; k++) ws[k] = wg[t0 + k];
        #pragma unroll
        for (int k = 0; k < 16; k++) xs[k] = xb[(size_t)(t0 + k) * D_];
        #pragma unroll
        for (int k = 0; k < 16; k++) {
            int idx = __float_as_int(ws[k].y) * 32 + lane + (k & 1) * 2048;
            aw[idx] = fmaf(ws[k].x, xs[k], aw[idx]);
        }
    }
    __syncthreads();

    // Flush: sum 8 buffers per (g, col), apply norm_w, write partial p.
    float* pout = g_p2[z] + (size_t)b * G_ * D_ + (size_t)ch * 32;
    for (int i = tid; i < G_ * 32; i += 128) {
        int g = i >> 5, c = i & 31;
        float s = 0.f;
        #pragma unroll
        for (int ww = 0; ww < 4; ww++)
            #pragma unroll
            for (int q = 0; q < 2; q++)
                s += acc[ww * 4096 + q * 2048 + g * 32 + c];
        pout[(size_t)g * D_ + c] = s * norm_w[ch * 32 + c];
    }
}

// ---------------------------------------------------------------------------
// Kernel 4: out = p @ Wv^T, split-K=4.  M=512, N=1024, K=1024.
// A is read as p2[0] + p2[1] (token-split partial sum folded into load).
// ---------------------------------------------------------------------------
__global__ void __launch_bounds__(256) gemm_kernel(const float* __restrict__ Wv) {
    __shared__ float As[8][128];
    __shared__ float Bs[8][128];
    int tid = threadIdx.x;
    int bn = blockIdx.x, bm = blockIdx.y, ks = blockIdx.z;
    int row = tid >> 1;            // 0..127 (loader row)
    int kq  = (tid & 1) * 4;       // loader k quad
    int tx = tid & 15, ty = tid >> 4;

    size_t aoff = (size_t)(bm * 128 + row) * D_ + ks * 256 + kq;
    const float* Ag0 = g_p2[0] + aoff;
    const float* Ag1 = g_p2[1] + aoff;
    const float* Bg  = Wv + (size_t)(bn * 128 + row) * D_ + ks * 256 + kq;

    u64 acc2[8][4];
    #pragma unroll
    for (int r = 0; r < 8; r++)
        #pragma unroll
        for (int c = 0; c < 4; c++) acc2[r][c] = 0ull;

    for (int k0 = 0; k0 < 256; k0 += 8) {
        float4 a0v = *(const float4*)(Ag0 + k0);
        float4 a1v = *(const float4*)(Ag1 + k0);
        float4 bv  = *(const float4*)(Bg + k0);
        float4 av  = make_float4(a0v.x + a1v.x, a0v.y + a1v.y,
                                 a0v.z + a1v.z, a0v.w + a1v.w);
        __syncthreads();
        As[kq + 0][row] = av.x; As[kq + 1][row] = av.y;
        As[kq + 2][row] = av.z; As[kq + 3][row] = av.w;
        Bs[kq + 0][row] = bv.x; Bs[kq + 1][row] = bv.y;
        Bs[kq + 2][row] = bv.z; Bs[kq + 3][row] = bv.w;
        __syncthreads();
        #pragma unroll
        for (int kk = 0; kk < 8; kk++) {
            float4 a0 = *(const float4*)&As[kk][ty * 8];
            float4 a1 = *(const float4*)&As[kk][ty * 8 + 4];
            ulonglong2 bb0 = *(const ulonglong2*)&Bs[kk][tx * 8];
            ulonglong2 bb1 = *(const ulonglong2*)&Bs[kk][tx * 8 + 4];
            u64 bc[4] = {bb0.x, bb0.y, bb1.x, bb1.y};
            float a[8] = {a0.x, a0.y, a0.z, a0.w, a1.x, a1.y, a1.z, a1.w};
            #pragma unroll
            for (int r = 0; r < 8; r++) {
                u64 ar = pack2(a[r]);
                #pragma unroll
                for (int c = 0; c < 4; c++)
                    acc2[r][c] = fma2(ar, bc[c], acc2[r][c]);
            }
        }
    }

    float* op = g_out_part[ks] + (size_t)(bm * 128 + ty * 8) * D_ + bn * 128 + tx * 8;
    #pragma unroll
    for (int r = 0; r < 8; r++) {
        *(ulonglong2*)(op + (size_t)r * D_)     = make_ulonglong2(acc2[r][0], acc2[r][1]);
        *(ulonglong2*)(op + (size_t)r * D_ + 4) = make_ulonglong2(acc2[r][2], acc2[r][3]);
    }
}

// Kernel 5: fixed-order split-K reduction into d_out
__global__ void gemm_reduce_kernel(float* __restrict__ out) {
    int idx = blockIdx.x * 256 + threadIdx.x;
    if (idx < BG_ * D_) {
        float s = g_out_part[0][idx] + g_out_part[1][idx]
                + g_out_part[2][idx] + g_out_part[3][idx];
        out[idx] = s;
    }
}

// ---------------------------------------------------------------------------
// Launch — 6 launches; pool sits at index 3 (ncu's sampled launch)
// ---------------------------------------------------------------------------
extern "C" void kernel_launch(void* const* d_in, const int* in_sizes, int n_in,
                              void* d_out, int out_size) {
    const float* x = nullptr;
    const void*  gid = nullptr;
    const float* query = nullptr;
    const float* norm_w = nullptr;
    const float* Wk = nullptr;
    const float* Wv = nullptr;

    for (int i = 0; i < n_in; i++) {
        int s = in_sizes[i];
        if (s == B_ * T_ * D_)      x = (const float*)d_in[i];
        else if (s == BT_)          gid = d_in[i];
        else if (s == D_) {
            if (!query) query = (const float*)d_in[i];
            else        norm_w = (const float*)d_in[i];
        } else if (s == D_ * D_) {
            if (!Wk) Wk = (const float*)d_in[i];
            else     Wv = (const float*)d_in[i];
        }
    }
    if (!x || !gid || !query || !norm_w || !Wk || !Wv) return;

    float* out = (float*)d_out;
    (void)out_size;

    cudaFuncSetAttribute(pool_kernel,
                         cudaFuncAttributeMaxDynamicSharedMemorySize, 65536);

    qk_kernel<<<64, 256>>>(query, Wk, norm_w);                 // 0
    token_stats_kernel<<<BT_ / 8, 256>>>(x);                   // 1
    seg_softmax_kernel<<<BG_, 128>>>((const unsigned int*)gid);// 2
    pool_kernel<<<dim3(32, 8, 2), 128, 65536>>>(x, norm_w);    // 3  <- profiled
    gemm_kernel<<<dim3(8, 4, 4), 256>>>(Wv);                   // 4
    gemm_reduce_kernel<<<(BG_ * D_ + 255) / 256, 256>>>(out);  // 5
}

// round 7
// speedup vs baseline: 2.7383x; 1.4532x over previous
#include <cuda_runtime.h>
#include <cstdint>
#include <cstddef>

// Problem constants (AttentionPool: B=8, T=4096, D=1024, G=64)
#define B_  8
#define T_  4096
#define D_  1024
#define G_  64
#define BT_ (B_ * T_)           // 32768 tokens
#define BG_ (B_ * G_)           // 512 (b,g) pairs
#define EPS_ 1.1920928955078125e-07f   // finfo(float32).eps
#define INV_SQRT_D_ (1.0f / 32.0f)

typedef unsigned long long u64;

// ---------------------------------------------------------------------------
// Device scratch (static — no allocations allowed)
// ---------------------------------------------------------------------------
__device__ float  g_qkd[D_];                // norm_w * (Wk^T q)
__device__ float  g_score[BT_];             // per-token score
__device__ float  g_invrms[BT_];            // per-token 1/rms
__device__ float2 g_wg[BT_];                // {coef, group_as_bits} per token
__device__ float  g_p2[2][BG_ * D_];        // pooled h partials (token split)
__device__ float  g_out_part[4][BG_ * D_];  // split-K GEMM partials

// ---------------------------------------------------------------------------
// helpers
// ---------------------------------------------------------------------------
__device__ __forceinline__ u64 pack2(float v) {
    u64 r; asm("mov.b64 %0, {%1, %1};" : "=l"(r) : "f"(v)); return r;
}
__device__ __forceinline__ u64 fma2(u64 a, u64 b, u64 c) {
    u64 d; asm("fma.rn.f32x2 %0, %1, %2, %3;" : "=l"(d) : "l"(a), "l"(b), "l"(c));
    return d;
}
__device__ __forceinline__ void cp16(uint32_t smem_dst, const void* gsrc) {
    asm volatile("cp.async.cg.shared.global [%0], [%1], 16;"
                 :: "r"(smem_dst), "l"(gsrc));
}
__device__ __forceinline__ void cp_commit() {
    asm volatile("cp.async.commit_group;");
}
template <int N>
__device__ __forceinline__ void cp_wait() {
    asm volatile("cp.async.wait_group %0;" :: "n"(N));
}

// ---------------------------------------------------------------------------
// Kernel 0: fused qk GEMV  qkd[d] = norm_w[d] * sum_e query[e] * Wk[e,d]
// ---------------------------------------------------------------------------
__global__ void __launch_bounds__(256) qk_kernel(
    const float* __restrict__ query, const float* __restrict__ Wk,
    const float* __restrict__ norm_w) {
    int di = threadIdx.x & 15;
    int eg = threadIdx.x >> 4;
    int d  = blockIdx.x * 16 + di;
    float s = 0.f;
    #pragma unroll 8
    for (int e = eg; e < D_; e += 16) s += query[e] * Wk[(size_t)e * D_ + d];
    __shared__ float red[16][17];
    red[eg][di] = s;
    __syncthreads();
    if (threadIdx.x < 16) {
        int dd = blockIdx.x * 16 + threadIdx.x;
        float t = 0.f;
        #pragma unroll
        for (int i = 0; i < 16; i++) t += red[i][threadIdx.x];
        g_qkd[dd] = t * norm_w[dd];
    }
}

// ---------------------------------------------------------------------------
// Kernel 1: per-token stats, warp-per-token. 8 warps/block, no barriers.
// ---------------------------------------------------------------------------
__global__ void __launch_bounds__(256) token_stats_kernel(const float* __restrict__ x) {
    int tok  = blockIdx.x * 8 + (threadIdx.x >> 5);
    int lane = threadIdx.x & 31;
    const float4* xt = (const float4*)(x + (size_t)tok * D_);
    const float4* qk = (const float4*)g_qkd;

    float4 xv[8], qv[8];
    #pragma unroll
    for (int r = 0; r < 8; r++) xv[r] = xt[r * 32 + lane];
    #pragma unroll
    for (int r = 0; r < 8; r++) qv[r] = qk[r * 32 + lane];

    float ss = 0.f, dq = 0.f;
    #pragma unroll
    for (int r = 0; r < 8; r++) {
        float4 v = xv[r], q = qv[r];
        ss += v.x * v.x + v.y * v.y + v.z * v.z + v.w * v.w;
        dq += v.x * q.x + v.y * q.y + v.z * q.z + v.w * q.w;
    }
    #pragma unroll
    for (int o = 16; o; o >>= 1) {
        ss += __shfl_xor_sync(0xffffffffu, ss, o);
        dq += __shfl_xor_sync(0xffffffffu, dq, o);
    }
    if (lane == 0) {
        float ir = rsqrtf(ss * (1.0f / (float)D_) + EPS_);
        g_invrms[tok] = ir;
        g_score[tok]  = dq * ir * INV_SQRT_D_;
    }
}

// ---------------------------------------------------------------------------
// Kernel 2: segment softmax per (b,g) + per-token coef write.
// Inline dtype detect: OR of raw[2t+1], t<128 (<=1KB, in-bounds either way).
// ---------------------------------------------------------------------------
__global__ void __launch_bounds__(128) seg_softmax_kernel(const unsigned int* __restrict__ raw) {
    int b = blockIdx.x >> 6;
    int g = blockIdx.x & 63;
    int tid = threadIdx.x;

    unsigned int det = raw[2 * tid + 1];
    #pragma unroll
    for (int o = 16; o; o >>= 1) det |= __shfl_xor_sync(0xffffffffu, det, o);
    __shared__ unsigned int sdet[4];
    if ((tid & 31) == 0) sdet[tid >> 5] = det;
    __syncthreads();
    int is64 = ((sdet[0] | sdet[1] | sdet[2] | sdet[3]) == 0) ? 1 : 0;

    const float* sc = g_score + b * T_;
    int base = b * T_;

    float mx = -3.402823466e38f;
    for (int t = tid; t < T_; t += 128) {
        int gid = (int)(is64 ? raw[2 * (base + t)] : raw[base + t]);
        if (gid == g) mx = fmaxf(mx, sc[t]);
    }
    #pragma unroll
    for (int o = 16; o; o >>= 1) mx = fmaxf(mx, __shfl_xor_sync(0xffffffffu, mx, o));
    __shared__ float sm[4];
    if ((tid & 31) == 0) sm[tid >> 5] = mx;
    __syncthreads();
    mx = fmaxf(fmaxf(sm[0], sm[1]), fmaxf(sm[2], sm[3]));
    if (mx < -1e37f) mx = 0.f;   // empty group guard

    float sum = 0.f;
    for (int t = tid; t < T_; t += 128) {
        int gid = (int)(is64 ? raw[2 * (base + t)] : raw[base + t]);
        if (gid == g) sum += __expf(sc[t] - mx);
    }
    #pragma unroll
    for (int o = 16; o; o >>= 1) sum += __shfl_xor_sync(0xffffffffu, sum, o);
    __shared__ float ssum[4];
    if ((tid & 31) == 0) ssum[tid >> 5] = sum;
    __syncthreads();
    float S = ssum[0] + ssum[1] + ssum[2] + ssum[3];
    float rden = (S > 0.f) ? (1.0f / S) : 0.f;

    float gb = __int_as_float(g);
    for (int t = tid; t < T_; t += 128) {
        int gid = (int)(is64 ? raw[2 * (base + t)] : raw[base + t]);
        if (gid == g) {
            float c = __expf(sc[t] - mx) * rden * g_invrms[base + t];
            g_wg[base + t] = make_float2(c, gb);
        }
    }
}

// ---------------------------------------------------------------------------
// Kernel 3: group pooling  p[b,g,d] += coef * x[b,t,d], *norm_w at flush.
// v3: cp.async-staged x tiles (register-free MLP).
// smem: acc [4w][2 parity][2048] = 64KB; x stage 3 x 64tok x 32col = 24KB;
// wg stage 3 x 64 float2 = 1.5KB. Total ~90KB -> 2 CTAs/SM, 48KB/SM in flight.
// Grid (32 col-chunks, 8 batches, 2 token-splits) = 512 CTAs.
// ---------------------------------------------------------------------------
#define POOL_ACC_F   (4 * 2 * 2048)          // 16384 floats
#define POOL_SX_F    (3 * 64 * 32)           // 6144 floats
#define POOL_SWG_F   (3 * 64 * 2)            // 384 floats
#define POOL_SMEM_B  ((POOL_ACC_F + POOL_SX_F + POOL_SWG_F) * 4)

__global__ void __launch_bounds__(128) pool_kernel(
    const float* __restrict__ x, const float* __restrict__ norm_w) {
    extern __shared__ float smem[];
    float* acc = smem;                        // 16384 floats
    float* sx  = smem + POOL_ACC_F;           // 3 x 2048 floats
    float* swg = sx + POOL_SX_F;              // 3 x 128 floats

    int tid  = threadIdx.x;
    int lane = tid & 31;
    int w    = tid >> 5;
    int ch   = blockIdx.x;           // 0..31 (column chunk of 32)
    int b    = blockIdx.y;           // 0..7
    int z    = blockIdx.z;           // 0..1 (token split: 32 tiles of 64 tokens)

    for (int i = tid; i < POOL_ACC_F; i += 128) acc[i] = 0.f;

    const float*  xb  = x + (size_t)b * T_ * D_ + (size_t)ch * 32;
    const float2* wgb = g_wg + b * T_;
    int tbase = z * 2048;            // first token of this split

    uint32_t sx_base  = (uint32_t)__cvta_generic_to_shared(sx);
    uint32_t swg_base = (uint32_t)__cvta_generic_to_shared(swg);

    // issue one tile's loads into stage buffer s
    auto issue = [&](int tile, int s) {
        int t0 = tbase + tile * 64;
        // x: 64 rows x 128B; 128 threads x 16B = 2KB/pass, 4 passes
        int rrow = tid >> 3;          // 0..15
        int rcol = (tid & 7) * 4;     // 0,4,..28
        uint32_t dst = sx_base + (uint32_t)(s * 2048 + rrow * 32 + rcol) * 4u;
        const float* src = xb + (size_t)(t0 + rrow) * D_ + rcol;
        #pragma unroll
        for (int p = 0; p < 4; p++)
            cp16(dst + p * 16u * 32u * 4u, src + (size_t)p * 16 * D_);
        // wg: 64 float2 = 512B; threads 0..31 x 16B
        if (tid < 32) {
            uint32_t d2 = swg_base + (uint32_t)(s * 128) * 4u + (uint32_t)tid * 16u;
            cp16(d2, (const char*)(wgb + t0) + tid * 16);
        }
    };

    // prologue: 3 tiles in flight (also covers the acc-zeroing barrier)
    issue(0, 0); cp_commit();
    issue(1, 1); cp_commit();
    issue(2, 2); cp_commit();

    float* aw = acc + w * 4096;
    for (int i = 0; i < 32; i++) {
        cp_wait<2>();
        __syncthreads();              // tile i visible to all; acc zeroed (i==0)
        int s = i - (i / 3) * 3;      // i % 3
        const float*  sxb  = sx + s * 2048;
        const float2* swgb = (const float2*)(swg + s * 128);
        int lt0 = w * 16;
        #pragma unroll
        for (int k = 0; k < 16; k++) {
            float2 wk = swgb[lt0 + k];             // LDS.64 broadcast
            float  xv = sxb[(lt0 + k) * 32 + lane]; // conflict-free
            int idx = __float_as_int(wk.y) * 32 + lane + (k & 1) * 2048;
            aw[idx] = fmaf(wk.x, xv, aw[idx]);
        }
        __syncthreads();              // all warps done with buffer s
        if (i + 3 < 32) issue(i + 3, s);
        cp_commit();                  // commit (possibly empty) group
    }

    // Flush: sum 8 copies per (g, col), apply norm_w, write partial p.
    float* pout = g_p2[z] + (size_t)b * G_ * D_ + (size_t)ch * 32;
    for (int i = tid; i < G_ * 32; i += 128) {
        int g = i >> 5, c = i & 31;
        float s = 0.f;
        #pragma unroll
        for (int ww = 0; ww < 4; ww++)
            #pragma unroll
            for (int q = 0; q < 2; q++)
                s += acc[ww * 4096 + q * 2048 + g * 32 + c];
        pout[(size_t)g * D_ + c] = s * norm_w[ch * 32 + c];
    }
}

// ---------------------------------------------------------------------------
// Kernel 4: out = p @ Wv^T, split-K=4.  M=512, N=1024, K=1024.
// A is read as p2[0] + p2[1] (token-split partial sum folded into load).
// ---------------------------------------------------------------------------
__global__ void __launch_bounds__(256) gemm_kernel(const float* __restrict__ Wv) {
    __shared__ float As[8][128];
    __shared__ float Bs[8][128];
    int tid = threadIdx.x;
    int bn = blockIdx.x, bm = blockIdx.y, ks = blockIdx.z;
    int row = tid >> 1;            // 0..127 (loader row)
    int kq  = (tid & 1) * 4;       // loader k quad
    int tx = tid & 15, ty = tid >> 4;

    size_t aoff = (size_t)(bm * 128 + row) * D_ + ks * 256 + kq;
    const float* Ag0 = g_p2[0] + aoff;
    const float* Ag1 = g_p2[1] + aoff;
    const float* Bg  = Wv + (size_t)(bn * 128 + row) * D_ + ks * 256 + kq;

    u64 acc2[8][4];
    #pragma unroll
    for (int r = 0; r < 8; r++)
        #pragma unroll
        for (int c = 0; c < 4; c++) acc2[r][c] = 0ull;

    for (int k0 = 0; k0 < 256; k0 += 8) {
        float4 a0v = *(const float4*)(Ag0 + k0);
        float4 a1v = *(const float4*)(Ag1 + k0);
        float4 bv  = *(const float4*)(Bg + k0);
        float4 av  = make_float4(a0v.x + a1v.x, a0v.y + a1v.y,
                                 a0v.z + a1v.z, a0v.w + a1v.w);
        __syncthreads();
        As[kq + 0][row] = av.x; As[kq + 1][row] = av.y;
        As[kq + 2][row] = av.z; As[kq + 3][row] = av.w;
        Bs[kq + 0][row] = bv.x; Bs[kq + 1][row] = bv.y;
        Bs[kq + 2][row] = bv.z; Bs[kq + 3][row] = bv.w;
        __syncthreads();
        #pragma unroll
        for (int kk = 0; kk < 8; kk++) {
            float4 a0 = *(const float4*)&As[kk][ty * 8];
            float4 a1 = *(const float4*)&As[kk][ty * 8 + 4];
            ulonglong2 bb0 = *(const ulonglong2*)&Bs[kk][tx * 8];
            ulonglong2 bb1 = *(const ulonglong2*)&Bs[kk][tx * 8 + 4];
            u64 bc[4] = {bb0.x, bb0.y, bb1.x, bb1.y};
            float a[8] = {a0.x, a0.y, a0.z, a0.w, a1.x, a1.y, a1.z, a1.w};
            #pragma unroll
            for (int r = 0; r < 8; r++) {
                u64 ar = pack2(a[r]);
                #pragma unroll
                for (int c = 0; c < 4; c++)
                    acc2[r][c] = fma2(ar, bc[c], acc2[r][c]);
            }
        }
    }

    float* op = g_out_part[ks] + (size_t)(bm * 128 + ty * 8) * D_ + bn * 128 + tx * 8;
    #pragma unroll
    for (int r = 0; r < 8; r++) {
        *(ulonglong2*)(op + (size_t)r * D_)     = make_ulonglong2(acc2[r][0], acc2[r][1]);
        *(ulonglong2*)(op + (size_t)r * D_ + 4) = make_ulonglong2(acc2[r][2], acc2[r][3]);
    }
}

// Kernel 5: fixed-order split-K reduction into d_out
__global__ void gemm_reduce_kernel(float* __restrict__ out) {
    int idx = blockIdx.x * 256 + threadIdx.x;
    if (idx < BG_ * D_) {
        float s = g_out_part[0][idx] + g_out_part[1][idx]
                + g_out_part[2][idx] + g_out_part[3][idx];
        out[idx] = s;
    }
}

// ---------------------------------------------------------------------------
// Launch — 6 launches; pool sits at index 3 (ncu's sampled launch)
// ---------------------------------------------------------------------------
extern "C" void kernel_launch(void* const* d_in, const int* in_sizes, int n_in,
                              void* d_out, int out_size) {
    const float* x = nullptr;
    const void*  gid = nullptr;
    const float* query = nullptr;
    const float* norm_w = nullptr;
    const float* Wk = nullptr;
    const float* Wv = nullptr;

    for (int i = 0; i < n_in; i++) {
        int s = in_sizes[i];
        if (s == B_ * T_ * D_)      x = (const float*)d_in[i];
        else if (s == BT_)          gid = d_in[i];
        else if (s == D_) {
            if (!query) query = (const float*)d_in[i];
            else        norm_w = (const float*)d_in[i];
        } else if (s == D_ * D_) {
            if (!Wk) Wk = (const float*)d_in[i];
            else     Wv = (const float*)d_in[i];
        }
    }
    if (!x || !gid || !query || !norm_w || !Wk || !Wv) return;

    float* out = (float*)d_out;
    (void)out_size;

    cudaFuncSetAttribute(pool_kernel,
                         cudaFuncAttributeMaxDynamicSharedMemorySize, POOL_SMEM_B);

    qk_kernel<<<64, 256>>>(query, Wk, norm_w);                   // 0
    token_stats_kernel<<<BT_ / 8, 256>>>(x);                     // 1
    seg_softmax_kernel<<<BG_, 128>>>((const unsigned int*)gid);  // 2
    pool_kernel<<<dim3(32, 8, 2), 128, POOL_SMEM_B>>>(x, norm_w);// 3  <- profiled
    gemm_kernel<<<dim3(8, 4, 4), 256>>>(Wv);                     // 4
    gemm_reduce_kernel<<<(BG_ * D_ + 255) / 256, 256>>>(out);    // 5
}

// round 8
// speedup vs baseline: 2.8824x; 1.0526x over previous
#include <cuda_runtime.h>
#include <cstdint>
#include <cstddef>

// Problem constants (AttentionPool: B=8, T=4096, D=1024, G=64)
#define B_  8
#define T_  4096
#define D_  1024
#define G_  64
#define BT_ (B_ * T_)           // 32768 tokens
#define BG_ (B_ * G_)           // 512 (b,g) pairs
#define EPS_ 1.1920928955078125e-07f   // finfo(float32).eps
#define INV_SQRT_D_ (1.0f / 32.0f)

typedef unsigned long long u64;

// ---------------------------------------------------------------------------
// Device scratch (static — no allocations allowed)
// ---------------------------------------------------------------------------
__device__ float  g_qkd[D_];                // norm_w * (Wk^T q)
__device__ float  g_score[BT_];             // per-token score
__device__ float  g_invrms[BT_];            // per-token 1/rms
__device__ float2 g_wg[BT_];                // {coef, group_as_bits} per token
__device__ float  g_p4[4][BG_ * D_];        // pooled h partials (token split 4)
__device__ float  g_out_part[4][BG_ * D_];  // split-K GEMM partials

// ---------------------------------------------------------------------------
// helpers
// ---------------------------------------------------------------------------
__device__ __forceinline__ u64 pack2(float v) {
    u64 r; asm("mov.b64 %0, {%1, %1};" : "=l"(r) : "f"(v)); return r;
}
__device__ __forceinline__ u64 fma2(u64 a, u64 b, u64 c) {
    u64 d; asm("fma.rn.f32x2 %0, %1, %2, %3;" : "=l"(d) : "l"(a), "l"(b), "l"(c));
    return d;
}
__device__ __forceinline__ void cp16(uint32_t smem_dst, const void* gsrc) {
    asm volatile("cp.async.cg.shared.global [%0], [%1], 16;"
                 :: "r"(smem_dst), "l"(gsrc));
}
__device__ __forceinline__ void cp_commit() {
    asm volatile("cp.async.commit_group;");
}
template <int N>
__device__ __forceinline__ void cp_wait() {
    asm volatile("cp.async.wait_group %0;" :: "n"(N));
}

// ---------------------------------------------------------------------------
// Kernel 0: fused qk GEMV  qkd[d] = norm_w[d] * sum_e query[e] * Wk[e,d]
// ---------------------------------------------------------------------------
__global__ void __launch_bounds__(256) qk_kernel(
    const float* __restrict__ query, const float* __restrict__ Wk,
    const float* __restrict__ norm_w) {
    int di = threadIdx.x & 15;
    int eg = threadIdx.x >> 4;
    int d  = blockIdx.x * 16 + di;
    float s = 0.f;
    #pragma unroll 8
    for (int e = eg; e < D_; e += 16) s += query[e] * Wk[(size_t)e * D_ + d];
    __shared__ float red[16][17];
    red[eg][di] = s;
    __syncthreads();
    if (threadIdx.x < 16) {
        int dd = blockIdx.x * 16 + threadIdx.x;
        float t = 0.f;
        #pragma unroll
        for (int i = 0; i < 16; i++) t += red[i][threadIdx.x];
        g_qkd[dd] = t * norm_w[dd];
    }
}

// ---------------------------------------------------------------------------
// Kernel 1: per-token stats v2 — 2 tokens per warp, 16 front-batched LDG.128
// (2KB in flight per warp). launch_bounds(256,1) gives ptxas reg headroom
// so loads stay batched instead of being sunk (the v1 failure mode).
// ---------------------------------------------------------------------------
__global__ void __launch_bounds__(256, 1) token_stats_kernel(const float* __restrict__ x) {
    int w    = threadIdx.x >> 5;
    int lane = threadIdx.x & 31;
    int tok0 = blockIdx.x * 16 + w * 2;
    int tok1 = tok0 + 1;
    const float4* xt0 = (const float4*)(x + (size_t)tok0 * D_);
    const float4* xt1 = (const float4*)(x + (size_t)tok1 * D_);
    const float4* qk  = (const float4*)g_qkd;

    float4 a[8], c[8];
    #pragma unroll
    for (int r = 0; r < 8; r++) a[r] = xt0[r * 32 + lane];
    #pragma unroll
    for (int r = 0; r < 8; r++) c[r] = xt1[r * 32 + lane];

    float ss0 = 0.f, dq0 = 0.f, ss1 = 0.f, dq1 = 0.f;
    #pragma unroll
    for (int r = 0; r < 8; r++) {
        float4 q = qk[r * 32 + lane];    // L1-resident (4KB, shared by all)
        float4 v = a[r];
        ss0 += v.x * v.x + v.y * v.y + v.z * v.z + v.w * v.w;
        dq0 += v.x * q.x + v.y * q.y + v.z * q.z + v.w * q.w;
        float4 u = c[r];
        ss1 += u.x * u.x + u.y * u.y + u.z * u.z + u.w * u.w;
        dq1 += u.x * q.x + u.y * q.y + u.z * q.z + u.w * q.w;
    }
    #pragma unroll
    for (int o = 16; o; o >>= 1) {
        ss0 += __shfl_xor_sync(0xffffffffu, ss0, o);
        dq0 += __shfl_xor_sync(0xffffffffu, dq0, o);
        ss1 += __shfl_xor_sync(0xffffffffu, ss1, o);
        dq1 += __shfl_xor_sync(0xffffffffu, dq1, o);
    }
    if (lane == 0) {
        float ir0 = rsqrtf(ss0 * (1.0f / (float)D_) + EPS_);
        g_invrms[tok0] = ir0;
        g_score[tok0]  = dq0 * ir0 * INV_SQRT_D_;
        float ir1 = rsqrtf(ss1 * (1.0f / (float)D_) + EPS_);
        g_invrms[tok1] = ir1;
        g_score[tok1]  = dq1 * ir1 * INV_SQRT_D_;
    }
}

// ---------------------------------------------------------------------------
// Kernel 2: segment softmax per (b,g) + per-token coef write.
// Inline dtype detect: OR of raw[2t+1], t<128 (<=1KB, in-bounds either way).
// ---------------------------------------------------------------------------
__global__ void __launch_bounds__(128) seg_softmax_kernel(const unsigned int* __restrict__ raw) {
    int b = blockIdx.x >> 6;
    int g = blockIdx.x & 63;
    int tid = threadIdx.x;

    unsigned int det = raw[2 * tid + 1];
    #pragma unroll
    for (int o = 16; o; o >>= 1) det |= __shfl_xor_sync(0xffffffffu, det, o);
    __shared__ unsigned int sdet[4];
    if ((tid & 31) == 0) sdet[tid >> 5] = det;
    __syncthreads();
    int is64 = ((sdet[0] | sdet[1] | sdet[2] | sdet[3]) == 0) ? 1 : 0;

    const float* sc = g_score + b * T_;
    int base = b * T_;

    float mx = -3.402823466e38f;
    for (int t = tid; t < T_; t += 128) {
        int gid = (int)(is64 ? raw[2 * (base + t)] : raw[base + t]);
        if (gid == g) mx = fmaxf(mx, sc[t]);
    }
    #pragma unroll
    for (int o = 16; o; o >>= 1) mx = fmaxf(mx, __shfl_xor_sync(0xffffffffu, mx, o));
    __shared__ float sm[4];
    if ((tid & 31) == 0) sm[tid >> 5] = mx;
    __syncthreads();
    mx = fmaxf(fmaxf(sm[0], sm[1]), fmaxf(sm[2], sm[3]));
    if (mx < -1e37f) mx = 0.f;   // empty group guard

    float sum = 0.f;
    for (int t = tid; t < T_; t += 128) {
        int gid = (int)(is64 ? raw[2 * (base + t)] : raw[base + t]);
        if (gid == g) sum += __expf(sc[t] - mx);
    }
    #pragma unroll
    for (int o = 16; o; o >>= 1) sum += __shfl_xor_sync(0xffffffffu, sum, o);
    __shared__ float ssum[4];
    if ((tid & 31) == 0) ssum[tid >> 5] = sum;
    __syncthreads();
    float S = ssum[0] + ssum[1] + ssum[2] + ssum[3];
    float rden = (S > 0.f) ? (1.0f / S) : 0.f;

    float gb = __int_as_float(g);
    for (int t = tid; t < T_; t += 128) {
        int gid = (int)(is64 ? raw[2 * (base + t)] : raw[base + t]);
        if (gid == g) {
            float c = __expf(sc[t] - mx) * rden * g_invrms[base + t];
            g_wg[base + t] = make_float2(c, gb);
        }
    }
}

// ---------------------------------------------------------------------------
// Kernel 3: group pooling v4.
// - S=4 cp.async ring, ONE barrier per tile, issue-before-compute
//   (3 tiles / 25.5KB per CTA in flight during compute).
// - Provably-disjoint parity regions: idx = ((g*32+lane) & 2047) + (k&1)*2048
//   lets ptxas overlap pairs of scatter RMWs (chain 560 -> ~300 cyc/tile).
// - z-split 4 (1024 CTAs x 16 tiles) for finer wave granularity.
// smem: acc 64KB + stages 4x(8KB x + 0.5KB wg) = ~98KB -> 2 CTAs/SM.
// ---------------------------------------------------------------------------
#define POOL_S      4
#define POOL_ACC_F  (4 * 2 * 2048)           // 16384 floats
#define POOL_SX_F   (POOL_S * 64 * 32)       // 8192 floats
#define POOL_SWG_F  (POOL_S * 64 * 2)        // 512 floats
#define POOL_SMEM_B ((POOL_ACC_F + POOL_SX_F + POOL_SWG_F) * 4)

__global__ void __launch_bounds__(128) pool_kernel(
    const float* __restrict__ x, const float* __restrict__ norm_w) {
    extern __shared__ float smem[];
    float* acc = smem;                        // 16384 floats
    float* sx  = smem + POOL_ACC_F;           // 4 x 2048 floats
    float* swg = sx + POOL_SX_F;              // 4 x 128 floats

    int tid  = threadIdx.x;
    int lane = tid & 31;
    int w    = tid >> 5;
    int ch   = blockIdx.x;           // 0..31 (column chunk of 32)
    int b    = blockIdx.y;           // 0..7
    int z    = blockIdx.z;           // 0..3 (token split: 16 tiles of 64 tokens)

    for (int i = tid; i < POOL_ACC_F; i += 128) acc[i] = 0.f;

    const float*  xb  = x + (size_t)b * T_ * D_ + (size_t)ch * 32;
    const float2* wgb = g_wg + b * T_;
    int tbase = z * 1024;            // first token of this split

    uint32_t sx_base  = (uint32_t)__cvta_generic_to_shared(sx);
    uint32_t swg_base = (uint32_t)__cvta_generic_to_shared(swg);

    // issue one tile's loads into stage buffer s
    auto issue = [&](int tile, int s) {
        int t0 = tbase + tile * 64;
        int rrow = tid >> 3;          // 0..15
        int rcol = (tid & 7) * 4;     // 0,4,..28
        uint32_t dst = sx_base + (uint32_t)(s * 2048 + rrow * 32 + rcol) * 4u;
        const float* src = xb + (size_t)(t0 + rrow) * D_ + rcol;
        #pragma unroll
        for (int p = 0; p < 4; p++)
            cp16(dst + p * 16u * 32u * 4u, src + (size_t)p * 16 * D_);
        if (tid < 32) {
            uint32_t d2 = swg_base + (uint32_t)(s * 128) * 4u + (uint32_t)tid * 16u;
            cp16(d2, (const char*)(wgb + t0) + tid * 16);
        }
    };

    issue(0, 0); cp_commit();
    issue(1, 1); cp_commit();
    issue(2, 2); cp_commit();

    float* aw = acc + w * 4096;
    for (int i = 0; i < 16; i++) {
        cp_wait<2>();                 // tile i resident
        __syncthreads();              // visible to all; slot (i-1)&3 free; acc zeroed (i==0)
        if (i + 3 < 16) issue(i + 3, (i + 3) & 3);
        cp_commit();                  // one group per iteration (maybe empty)
        int s = i & 3;
        const float*  sxb  = sx + s * 2048;
        const float2* swgb = (const float2*)(swg + s * 128);
        int lt0 = w * 16;
        #pragma unroll
        for (int kb = 0; kb < 8; kb++) {
            float2 w0 = swgb[lt0 + 2 * kb];
            float2 w1 = swgb[lt0 + 2 * kb + 1];
            float  x0 = sxb[(lt0 + 2 * kb) * 32 + lane];
            float  x1 = sxb[(lt0 + 2 * kb + 1) * 32 + lane];
            // &2047 is a no-op (g<64) but PROVES the two regions disjoint,
            // so the compiler can overlap the two RMW chains.
            int i0 = ((__float_as_int(w0.y) * 32 + lane) & 2047);
            int i1 = ((__float_as_int(w1.y) * 32 + lane) & 2047) + 2048;
            float v0 = aw[i0];
            float v1 = aw[i1];
            aw[i0] = fmaf(w0.x, x0, v0);
            aw[i1] = fmaf(w1.x, x1, v1);
        }
    }
    __syncthreads();                  // all compute done before cross-warp flush

    // Flush: sum 8 copies per (g, col), apply norm_w, write partial p.
    float* pout = g_p4[z] + (size_t)b * G_ * D_ + (size_t)ch * 32;
    for (int i = tid; i < G_ * 32; i += 128) {
        int g = i >> 5, c = i & 31;
        float s = 0.f;
        #pragma unroll
        for (int ww = 0; ww < 4; ww++)
            #pragma unroll
            for (int q = 0; q < 2; q++)
                s += acc[ww * 4096 + q * 2048 + g * 32 + c];
        pout[(size_t)g * D_ + c] = s * norm_w[ch * 32 + c];
    }
}

// ---------------------------------------------------------------------------
// Kernel 4: out = p @ Wv^T, split-K=4.  M=512, N=1024, K=1024.
// A is read as sum of 4 z-split partials (folded into the load).
// ---------------------------------------------------------------------------
__global__ void __launch_bounds__(256) gemm_kernel(const float* __restrict__ Wv) {
    __shared__ float As[8][128];
    __shared__ float Bs[8][128];
    int tid = threadIdx.x;
    int bn = blockIdx.x, bm = blockIdx.y, ks = blockIdx.z;
    int row = tid >> 1;            // 0..127 (loader row)
    int kq  = (tid & 1) * 4;       // loader k quad
    int tx = tid & 15, ty = tid >> 4;

    size_t aoff = (size_t)(bm * 128 + row) * D_ + ks * 256 + kq;
    const float* Bg = Wv + (size_t)(bn * 128 + row) * D_ + ks * 256 + kq;

    u64 acc2[8][4];
    #pragma unroll
    for (int r = 0; r < 8; r++)
        #pragma unroll
        for (int c = 0; c < 4; c++) acc2[r][c] = 0ull;

    for (int k0 = 0; k0 < 256; k0 += 8) {
        float4 a0v = *(const float4*)(g_p4[0] + aoff + k0);
        float4 a1v = *(const float4*)(g_p4[1] + aoff + k0);
        float4 a2v = *(const float4*)(g_p4[2] + aoff + k0);
        float4 a3v = *(const float4*)(g_p4[3] + aoff + k0);
        float4 bv  = *(const float4*)(Bg + k0);
        float4 av  = make_float4((a0v.x + a1v.x) + (a2v.x + a3v.x),
                                 (a0v.y + a1v.y) + (a2v.y + a3v.y),
                                 (a0v.z + a1v.z) + (a2v.z + a3v.z),
                                 (a0v.w + a1v.w) + (a2v.w + a3v.w));
        __syncthreads();
        As[kq + 0][row] = av.x; As[kq + 1][row] = av.y;
        As[kq + 2][row] = av.z; As[kq + 3][row] = av.w;
        Bs[kq + 0][row] = bv.x; Bs[kq + 1][row] = bv.y;
        Bs[kq + 2][row] = bv.z; Bs[kq + 3][row] = bv.w;
        __syncthreads();
        #pragma unroll
        for (int kk = 0; kk < 8; kk++) {
            float4 a0 = *(const float4*)&As[kk][ty * 8];
            float4 a1 = *(const float4*)&As[kk][ty * 8 + 4];
            ulonglong2 bb0 = *(const ulonglong2*)&Bs[kk][tx * 8];
            ulonglong2 bb1 = *(const ulonglong2*)&Bs[kk][tx * 8 + 4];
            u64 bc[4] = {bb0.x, bb0.y, bb1.x, bb1.y};
            float a[8] = {a0.x, a0.y, a0.z, a0.w, a1.x, a1.y, a1.z, a1.w};
            #pragma unroll
            for (int r = 0; r < 8; r++) {
                u64 ar = pack2(a[r]);
                #pragma unroll
                for (int c = 0; c < 4; c++)
                    acc2[r][c] = fma2(ar, bc[c], acc2[r][c]);
            }
        }
    }

    float* op = g_out_part[ks] + (size_t)(bm * 128 + ty * 8) * D_ + bn * 128 + tx * 8;
    #pragma unroll
    for (int r = 0; r < 8; r++) {
        *(ulonglong2*)(op + (size_t)r * D_)     = make_ulonglong2(acc2[r][0], acc2[r][1]);
        *(ulonglong2*)(op + (size_t)r * D_ + 4) = make_ulonglong2(acc2[r][2], acc2[r][3]);
    }
}

// Kernel 5: fixed-order split-K reduction into d_out
__global__ void gemm_reduce_kernel(float* __restrict__ out) {
    int idx = blockIdx.x * 256 + threadIdx.x;
    if (idx < BG_ * D_) {
        float s = g_out_part[0][idx] + g_out_part[1][idx]
                + g_out_part[2][idx] + g_out_part[3][idx];
        out[idx] = s;
    }
}

// ---------------------------------------------------------------------------
// Launch — 6 launches; pool at index 3 (ncu's sampled launch)
// ---------------------------------------------------------------------------
extern "C" void kernel_launch(void* const* d_in, const int* in_sizes, int n_in,
                              void* d_out, int out_size) {
    const float* x = nullptr;
    const void*  gid = nullptr;
    const float* query = nullptr;
    const float* norm_w = nullptr;
    const float* Wk = nullptr;
    const float* Wv = nullptr;

    for (int i = 0; i < n_in; i++) {
        int s = in_sizes[i];
        if (s == B_ * T_ * D_)      x = (const float*)d_in[i];
        else if (s == BT_)          gid = d_in[i];
        else if (s == D_) {
            if (!query) query = (const float*)d_in[i];
            else        norm_w = (const float*)d_in[i];
        } else if (s == D_ * D_) {
            if (!Wk) Wk = (const float*)d_in[i];
            else     Wv = (const float*)d_in[i];
        }
    }
    if (!x || !gid || !query || !norm_w || !Wk || !Wv) return;

    float* out = (float*)d_out;
    (void)out_size;

    cudaFuncSetAttribute(pool_kernel,
                         cudaFuncAttributeMaxDynamicSharedMemorySize, POOL_SMEM_B);

    qk_kernel<<<64, 256>>>(query, Wk, norm_w);                   // 0
    token_stats_kernel<<<BT_ / 16, 256>>>(x);                    // 1
    seg_softmax_kernel<<<BG_, 128>>>((const unsigned int*)gid);  // 2
    pool_kernel<<<dim3(32, 8, 4), 128, POOL_SMEM_B>>>(x, norm_w);// 3  <- profiled
    gemm_kernel<<<dim3(8, 4, 4), 256>>>(Wv);                     // 4
    gemm_reduce_kernel<<<(BG_ * D_ + 255) / 256, 256>>>(out);    // 5
}